// round 12
// baseline (speedup 1.0000x reference)
#include <cuda_runtime.h>
#include <cuda_fp16.h>
#include <cstdint>

// Quanvolution (2x2, 4 qubits): Zq = cos(pi*a_q + w_q);
//   ch0 = Z1*Z2*Z3, ch1 = Z0*Z1, ch2 = Z0*Z1*Z2, ch3 = Z0*Z1*Z2*Z3
//
// R12: stores via cp.async.bulk (TMA). Block (i,b) owns, for each channel ch,
// output rows [8i+ch, 8i+ch+8) — that span is contiguous (x-major planes) and
// both its start float-offset (ch*plane + (8i+ch)*223 == 4ch+24i mod 4 == 0)
// and size (8*223*4 = 7136 B) are 16B-aligned. Values are computed into a
// contiguous smem stage with vector STS, then bulk-copied by one thread.
// fp16 interleaved Z tables: T01[r][c]=(Z0(r,c),Z1(r,c+1)), T23 likewise.

#define H_IN 224
#define W_IN 224
#define L_OUT 223
#define PLANE 49729                      // 223*223
#define RPB 8                            // output rows per block per channel
#define TIR 12                           // input tile rows
#define TPITCH 224                       // half2 words per table row
#define T_WORDS (TIR * TPITCH)           // 2688
#define S_FLOATS (RPB * L_OUT)           // 1784
#define S_BYTES (4 * S_FLOATS * 4)       // 28544
#define T_BYTES (2 * T_WORDS * 4)        // 21504
#define W_OFF (S_BYTES + T_BYTES)
#define SMEM_TOTAL (W_OFF + 32)
#define PI_F 3.14159265358979323846f

__device__ __forceinline__ uint32_t smem_u32(const void* p) {
    return (uint32_t)__cvta_generic_to_shared(p);
}

__device__ __forceinline__ void stage_quad(float* Sc, int rl, int q,
                                           float v0, float v1, float v2, float v3) {
    if ((unsigned)rl >= 8u) return;
    const int off = rl * 223 + (q << 2);
    if (q == 55) {                       // y = 220..222 only
        Sc[off] = v0; Sc[off + 1] = v1; Sc[off + 2] = v2;
        return;
    }
    const int a = (-rl) & 3;             // == off & 3  (223 == -1 mod 4)
    if (a == 0) {
        *reinterpret_cast<float4*>(&Sc[off]) = make_float4(v0, v1, v2, v3);
    } else if (a == 2) {
        *reinterpret_cast<float2*>(&Sc[off])     = make_float2(v0, v1);
        *reinterpret_cast<float2*>(&Sc[off + 2]) = make_float2(v2, v3);
    } else {
        Sc[off] = v0;
        *reinterpret_cast<float2*>(&Sc[off + 1]) = make_float2(v1, v2);
        Sc[off + 3] = v3;
    }
}

__global__ __launch_bounds__(256) void quanv_main_kernel(
    const float* __restrict__ in,   // (64,1,224,224)
    const float* __restrict__ w,    // (1,4)
    float* __restrict__ out)        // (64,4,223,223)
{
    extern __shared__ __align__(16) unsigned char smem_raw[];
    float*   S   = reinterpret_cast<float*>(smem_raw);            // [4][1784]
    __half2* T01 = reinterpret_cast<__half2*>(smem_raw + S_BYTES);
    __half2* T23 = T01 + T_WORDS;
    float*   wtr = reinterpret_cast<float*>(smem_raw + W_OFF);    // cw[4], sw[4]

    const int tid = threadIdx.x;
    const int ib  = blockIdx.x;          // 0..27
    const int b   = blockIdx.y;
    const int X   = ib * RPB;

    const float* inb = in + (size_t)b * (H_IN * W_IN);

    if (tid < 4) {
        float s, c;
        __sincosf(__ldg(&w[tid]), &s, &c);
        wtr[tid] = c; wtr[4 + tid] = s;
    }

    // ---- Batched input loads: 3 passes; r = idx>>6, slot = idx&63, c = 4*slot.
    float4 vv[3]; float vx[3]; int rr[3], cc[3]; bool act[3];
    #pragma unroll
    for (int p = 0; p < 3; p++) {
        const int idx = tid + 256 * p;
        const int r = idx >> 6, slot = idx & 63;
        rr[p] = r; cc[p] = slot * 4; act[p] = (slot < 56);
        if (act[p]) {
            int gr = X + r; if (gr > 223) gr = 223;
            const float* rp = inb + gr * W_IN + cc[p];
            vv[p] = *reinterpret_cast<const float4*>(rp);
            int c4 = cc[p] + 4; if (c4 > 223) c4 = 223;
            vx[p] = __ldg(&inb[gr * W_IN + c4]);
        }
    }
    __syncthreads();   // B1: weights ready

    const float cw0 = wtr[0], cw1 = wtr[1], cw2 = wtr[2], cw3 = wtr[3];
    const float sw0 = wtr[4], sw1 = wtr[5], sw2 = wtr[6], sw3 = wtr[7];

    // ---- Build tables: per 4-col group 5 sincos, 16 folds, 2 STS.128.
    #pragma unroll
    for (int p = 0; p < 3; p++) {
        if (!act[p]) continue;
        float vs[5] = {vv[p].x, vv[p].y, vv[p].z, vv[p].w, vx[p]};
        float sn[5], cs[5];
        #pragma unroll
        for (int j = 0; j < 5; j++) __sincosf(vs[j] * PI_F, &sn[j], &cs[j]);
        __half2 w01[4], w23[4];
        #pragma unroll
        for (int j = 0; j < 4; j++) {
            const float z0 = fmaf(-sn[j],     sw0, cs[j]     * cw0);
            const float z1 = fmaf(-sn[j + 1], sw1, cs[j + 1] * cw1);
            const float z2 = fmaf(-sn[j],     sw2, cs[j]     * cw2);
            const float z3 = fmaf(-sn[j + 1], sw3, cs[j + 1] * cw3);
            w01[j] = __floats2half2_rn(z0, z1);
            w23[j] = __floats2half2_rn(z2, z3);
        }
        const int base = rr[p] * TPITCH + cc[p];
        *reinterpret_cast<uint4*>(&T01[base]) = *reinterpret_cast<uint4*>(w01);
        *reinterpret_cast<uint4*>(&T23[base]) = *reinterpret_cast<uint4*>(w23);
    }
    __syncthreads();   // B2: tables ready

    // ---- Consumer: tasks (xr, q), xr in [0,11), q in [0,56); y = 4q.
    #pragma unroll
    for (int p = 0; p < 3; p++) {
        const int idx = tid + 256 * p;
        if (idx < 11 * 64) {
            const int xr = idx >> 6, q = idx & 63;
            if (q < 56) {
                const int yq = q << 2;
                const uint4 ua = *reinterpret_cast<const uint4*>(&T01[xr * TPITCH + yq]);
                const uint4 ub = *reinterpret_cast<const uint4*>(&T23[(xr + 1) * TPITCH + yq]);
                const uint32_t aw[4] = {ua.x, ua.y, ua.z, ua.w};
                const uint32_t bw[4] = {ub.x, ub.y, ub.z, ub.w};
                float r0[4], r1[4], r2[4], r3[4];
                #pragma unroll
                for (int j = 0; j < 4; j++) {
                    const float2 z01 = __half22float2(*reinterpret_cast<const __half2*>(&aw[j]));
                    const float2 z23 = __half22float2(*reinterpret_cast<const __half2*>(&bw[j]));
                    const float p01 = z01.x * z01.y;
                    const float p23 = z23.x * z23.y;
                    r0[j] = z01.y * p23;          // ch0 = Z1 Z2 Z3
                    r1[j] = p01;                  // ch1 = Z0 Z1
                    r2[j] = p01 * z23.x;          // ch2 = Z0 Z1 Z2
                    r3[j] = p01 * p23;            // ch3 = Z0 Z1 Z2 Z3
                }
                stage_quad(S + 0 * S_FLOATS, xr - 0, q, r0[0], r0[1], r0[2], r0[3]);
                stage_quad(S + 1 * S_FLOATS, xr - 1, q, r1[0], r1[1], r1[2], r1[3]);
                stage_quad(S + 2 * S_FLOATS, xr - 2, q, r2[0], r2[1], r2[2], r2[3]);
                stage_quad(S + 3 * S_FLOATS, xr - 3, q, r3[0], r3[1], r3[2], r3[3]);
            }
        }
    }

    // ---- Head rows (global rows x < ch), only block ib==0: direct scalar.
    if (ib == 0) {
        const int px[6] = {0, 0, 0, 1, 1, 2};
        const int pc[6] = {1, 2, 3, 2, 3, 3};
        for (int idx = tid; idx < 6 * 256; idx += 256) {
            const int e = idx >> 8, y = idx & 255;
            if (y < L_OUT) {
                const int x = px[e], ch = pc[e];
                const float2 z01 = __half22float2(T01[x * TPITCH + y]);
                const float2 z23 = __half22float2(T23[(x + 1) * TPITCH + y]);
                const float p01 = z01.x * z01.y;
                const float p23 = z23.x * z23.y;
                float val;
                if (ch == 1)      val = p01;
                else if (ch == 2) val = p01 * z23.x;
                else              val = p01 * p23;
                out[((size_t)(b * 4 + ch)) * PLANE + (size_t)x * L_OUT + y] = val;
            }
        }
    }
    __syncthreads();   // B3: stage ready

    // ---- Bulk stores (TMA pipe) + tail scalars.
    const bool tail = (ib == 27);
    if (tid == 0) {
        asm volatile("fence.proxy.async.shared::cta;" ::: "memory");
        const uint32_t nbytes = tail ? (4 * L_OUT * 4) : (RPB * L_OUT * 4);
        #pragma unroll
        for (int ch = 0; ch < 4; ch++) {
            float* dst = out + ((size_t)(b * 4 + ch)) * PLANE + (size_t)(X + ch) * L_OUT;
            asm volatile(
                "cp.async.bulk.global.shared::cta.bulk_group [%0], [%1], %2;"
                :: "l"(dst), "r"(smem_u32(S + ch * S_FLOATS)), "r"(nbytes)
                : "memory");
        }
        asm volatile("cp.async.bulk.commit_group;" ::: "memory");
        asm volatile("cp.async.bulk.wait_group 0;" ::: "memory");
    }
    if (tail) {
        // remaining rows rl in [4, 7-ch): (ch,rl) = (0,4)(0,5)(0,6)(1,4)(1,5)(2,4)
        const int tch[6] = {0, 0, 0, 1, 1, 2};
        const int trl[6] = {4, 5, 6, 4, 5, 4};
        for (int idx = tid; idx < 6 * 256; idx += 256) {
            const int e = idx >> 8, y = idx & 255;
            if (y < L_OUT) {
                const int ch = tch[e], rl = trl[e];
                const int x = X + ch + rl;        // <= 222 by construction
                out[((size_t)(b * 4 + ch)) * PLANE + (size_t)x * L_OUT + y] =
                    S[ch * S_FLOATS + rl * 223 + y];
            }
        }
    }
}

extern "C" void kernel_launch(void* const* d_in, const int* in_sizes, int n_in,
                              void* d_out, int out_size) {
    const float* inputs = (const float*)d_in[0];   // (64,1,224,224) float32
    const float* weight = (const float*)d_in[1];   // (1,4) float32
    float* out = (float*)d_out;                    // (64,4,223,223) float32

    cudaFuncSetAttribute(quanv_main_kernel,
                         cudaFuncAttributeMaxDynamicSharedMemorySize, SMEM_TOTAL);

    dim3 grid(28, 64);    // 28 row-groups x 64 batch
    quanv_main_kernel<<<grid, 256, SMEM_TOTAL>>>(inputs, weight, out);
}

// round 15
// speedup vs baseline: 1.1765x; 1.1765x over previous
#include <cuda_runtime.h>
#include <cuda_fp16.h>
#include <cstdint>

// Quanvolution (2x2, 4 qubits): Zq = cos(pi*a_q + w_q);
//   ch0 = Z1*Z2*Z3, ch1 = Z0*Z1, ch2 = Z0*Z1*Z2, ch3 = Z0*Z1*Z2*Z3
//
// R13: vectorized direct stores. Output float offset ch*PLANE + x*223 + y
// satisfies offset mod 4 == (ch - x + y) mod 4, so for each (row, channel)
// quads starting at y = s + 4j with s = (x-ch)&3 are 16B-aligned -> STG.128.
// s is uniform per warp (x uniform) -> the switch(s) is non-divergent.
// fp16 interleaved Z tables (R10/R12): T01[r][c]=(Z0(r,c),Z1(r,c+1)),
// T23[r][c]=(Z2(r+1...),.. i.e. row r of T23 is used at pixel row r-1+1).
// Per (row, channel) only 3 edge y's need scalar stores (side pass).

#define H_IN 224
#define W_IN 224
#define L_OUT 223
#define PLANE 49729            // 223*223
#define RPB 8                  // output rows per block
#define TIR 9                  // input rows per block (halo)
#define TPITCH 224             // half2 words per table row (896B, 16B-mult)
#define PI_F 3.14159265358979323846f

// Store one aligned quad for a channel: values E(s), E(s+1), E(s+2), E(s+3)
// at float offset s from ptr. s in [0,3], uniform across the warp.
#define CASE_STORE(PTR, S, E)                                              \
    do {                                                                   \
        switch (S) {                                                       \
        case 0: *reinterpret_cast<float4*>((PTR) + 0) =                    \
                    make_float4(E(0), E(1), E(2), E(3)); break;            \
        case 1: *reinterpret_cast<float4*>((PTR) + 1) =                    \
                    make_float4(E(1), E(2), E(3), E(4)); break;            \
        case 2: *reinterpret_cast<float4*>((PTR) + 2) =                    \
                    make_float4(E(2), E(3), E(4), E(5)); break;            \
        default: *reinterpret_cast<float4*>((PTR) + 3) =                   \
                    make_float4(E(3), E(4), E(5), E(6)); break;            \
        }                                                                  \
    } while (0)

__global__ __launch_bounds__(256) void quanv_main_kernel(
    const float* __restrict__ in,   // (64,1,224,224)
    const float* __restrict__ w,    // (1,4)
    float* __restrict__ out)        // (64,4,223,223)
{
    __shared__ __half2 T01[TIR * TPITCH];   // 8064 B
    __shared__ __half2 T23[TIR * TPITCH];   // 8064 B
    __shared__ float wtr[8];

    const int tid = threadIdx.x;
    const int ib  = blockIdx.x;      // 0..27
    const int b   = blockIdx.y;
    const int X   = ib * RPB;

    const float* inb = in + (size_t)b * (H_IN * W_IN);

    // ---- Batched input loads: slots (r = idx>>6 in [0,9), g = idx&63 < 56),
    //      float4 at (row X+r, col 4g) + 1 scalar at col 4g+4 for interleave.
    float4 vv[3]; float vx[3]; int rr_[3], gg[3]; bool act[3];
    #pragma unroll
    for (int p = 0; p < 3; p++) {
        const int idx = tid + 256 * p;
        const int r = idx >> 6, g = idx & 63;
        rr_[p] = r; gg[p] = g;
        act[p] = (r < TIR) && (g < 56);
        if (act[p]) {
            int gr = X + r; if (gr > 223) gr = 223;
            const float* rp = inb + gr * W_IN + 4 * g;
            vv[p] = *reinterpret_cast<const float4*>(rp);
            int c4 = 4 * g + 4; if (c4 > 223) c4 = 223;
            vx[p] = __ldg(&inb[gr * W_IN + c4]);
        }
    }
    if (tid < 4) {
        float s, c;
        __sincosf(__ldg(&w[tid]), &s, &c);
        wtr[tid] = c; wtr[4 + tid] = s;
    }
    __syncthreads();   // weights ready

    const float cw0 = wtr[0], cw1 = wtr[1], cw2 = wtr[2], cw3 = wtr[3];
    const float sw0 = wtr[4], sw1 = wtr[5], sw2 = wtr[6], sw3 = wtr[7];

    // ---- Fold + pack + STS.128 (R12-proven).
    #pragma unroll
    for (int p = 0; p < 3; p++) {
        if (!act[p]) continue;
        float vs[5] = {vv[p].x, vv[p].y, vv[p].z, vv[p].w, vx[p]};
        float sn[5], cs[5];
        #pragma unroll
        for (int j = 0; j < 5; j++) __sincosf(vs[j] * PI_F, &sn[j], &cs[j]);
        __half2 w01[4], w23[4];
        #pragma unroll
        for (int j = 0; j < 4; j++) {
            const float z0 = fmaf(-sn[j],     sw0, cs[j]     * cw0);
            const float z1 = fmaf(-sn[j + 1], sw1, cs[j + 1] * cw1);
            const float z2 = fmaf(-sn[j],     sw2, cs[j]     * cw2);
            const float z3 = fmaf(-sn[j + 1], sw3, cs[j + 1] * cw3);
            w01[j] = __floats2half2_rn(z0, z1);
            w23[j] = __floats2half2_rn(z2, z3);
        }
        const int base = rr_[p] * TPITCH + 4 * gg[p];
        *reinterpret_cast<uint4*>(&T01[base]) = *reinterpret_cast<uint4*>(w01);
        *reinterpret_cast<uint4*>(&T23[base]) = *reinterpret_cast<uint4*>(w23);
    }
    __syncthreads();   // tables ready

    const size_t obase = (size_t)b * 4 * PLANE;

    // ---- Quad consumer: task (rx = tid>>6 + 4p in [0,8), q = tid&63 < 55).
    // Products for 7 consecutive y from 4q; 4 aligned STG.128 (one per ch).
    #pragma unroll
    for (int p = 0; p < 2; p++) {
        const int rx = (tid >> 6) + 4 * p;
        const int q  = tid & 63;
        const int x  = X + rx;
        if (q < 55 && x < L_OUT) {
            const int tb = rx * TPITCH + 4 * q;
            const uint4 a0 = *reinterpret_cast<const uint4*>(&T01[tb]);
            const uint4 a1 = *reinterpret_cast<const uint4*>(&T01[tb + 4]);
            const uint4 b0 = *reinterpret_cast<const uint4*>(&T23[tb + TPITCH]);
            const uint4 b1 = *reinterpret_cast<const uint4*>(&T23[tb + TPITCH + 4]);
            const uint32_t aw[8] = {a0.x, a0.y, a0.z, a0.w, a1.x, a1.y, a1.z, a1.w};
            const uint32_t bw[8] = {b0.x, b0.y, b0.z, b0.w, b1.x, b1.y, b1.z, b1.w};

            float p01[7], p23[7], z1v[7], z2v[7];
            #pragma unroll
            for (int i = 0; i < 7; i++) {
                const float2 z01 = __half22float2(*reinterpret_cast<const __half2*>(&aw[i]));
                const float2 z23 = __half22float2(*reinterpret_cast<const __half2*>(&bw[i]));
                p01[i] = z01.x * z01.y;
                p23[i] = z23.x * z23.y;
                z1v[i] = z01.y;
                z2v[i] = z23.x;
            }

            float* ob = out + obase + (size_t)x * L_OUT + 4 * q;
            int s;
            #define E0(i) (z1v[i] * p23[i])
            #define E1(i) (p01[i])
            #define E2(i) (p01[i] * z2v[i])
            #define E3(i) (p01[i] * p23[i])
            s = x & 3;        CASE_STORE(ob,             s, E0);   // ch0
            s = (x - 1) & 3;  CASE_STORE(ob + PLANE,     s, E1);   // ch1
            s = (x - 2) & 3;  CASE_STORE(ob + 2 * PLANE, s, E2);   // ch2
            s = (x - 3) & 3;  CASE_STORE(ob + 3 * PLANE, s, E3);   // ch3
            #undef E0
            #undef E1
            #undef E2
            #undef E3
        }
    }

    // ---- Edge scalars: per (row, ch) the 3 y's not covered by shifted quads:
    //      head [0,s) and tail [220+s, 223).
    if (tid < 128) {
        const int r = tid >> 4;          // 0..7
        const int e = tid & 15;
        if (e < 12) {
            const int ch = e & 3;
            const int k  = e >> 2;       // 0..2
            const int x  = X + r;
            if (x < L_OUT) {
                const int s = (x - ch) & 3;
                const int y = (k < s) ? k : (220 + k);
                const float2 z01 = __half22float2(T01[r * TPITCH + y]);
                const float2 z23 = __half22float2(T23[(r + 1) * TPITCH + y]);
                const float p01 = z01.x * z01.y;
                const float p23 = z23.x * z23.y;
                float val;
                if (ch == 0)      val = z01.y * p23;
                else if (ch == 1) val = p01;
                else if (ch == 2) val = p01 * z23.x;
                else              val = p01 * p23;
                out[obase + (size_t)ch * PLANE + (size_t)x * L_OUT + y] = val;
            }
        }
    }
}

extern "C" void kernel_launch(void* const* d_in, const int* in_sizes, int n_in,
                              void* d_out, int out_size) {
    const float* inputs = (const float*)d_in[0];   // (64,1,224,224) float32
    const float* weight = (const float*)d_in[1];   // (1,4) float32
    float* out = (float*)d_out;                    // (64,4,223,223) float32

    dim3 grid(28, 64);    // 28 row-groups x 64 batch
    quanv_main_kernel<<<grid, 256>>>(inputs, weight, out);
}

// round 16
// speedup vs baseline: 1.3043x; 1.1087x over previous
#include <cuda_runtime.h>
#include <cuda_fp16.h>
#include <cstdint>

// Quanvolution (2x2, 4 qubits): Zq = cos(pi*a_q + w_q);
//   ch0 = Z1*Z2*Z3, ch1 = Z0*Z1, ch2 = Z0*Z1*Z2, ch3 = Z0*Z1*Z2*Z3
//
// R16 = R13 (aligned STG.128 via per-channel shift s=(x-ch)&3; fp16
// interleaved tables T01[r][c]=(Z0(r,c),Z1(r,c+1)), T23 likewise) with a
// register diet: 2-pass loader (504 slots in 2x256) and launch_bounds(256,6)
// to push occupancy from 62% -> 75% theoretical. Latency-bound kernel: the
// occupancy is the lever (R9 occ81%=13.8us vs R13 occ51%=15.8us).

#define H_IN 224
#define W_IN 224
#define L_OUT 223
#define PLANE 49729            // 223*223
#define RPB 8                  // output rows per block
#define TIR 9                  // input rows per block (halo)
#define TPITCH 224             // half2 words per table row
#define PI_F 3.14159265358979323846f

#define CASE_STORE(PTR, S, E)                                              \
    do {                                                                   \
        switch (S) {                                                       \
        case 0: *reinterpret_cast<float4*>((PTR) + 0) =                    \
                    make_float4(E(0), E(1), E(2), E(3)); break;            \
        case 1: *reinterpret_cast<float4*>((PTR) + 1) =                    \
                    make_float4(E(1), E(2), E(3), E(4)); break;            \
        case 2: *reinterpret_cast<float4*>((PTR) + 2) =                    \
                    make_float4(E(2), E(3), E(4), E(5)); break;            \
        default: *reinterpret_cast<float4*>((PTR) + 3) =                   \
                    make_float4(E(3), E(4), E(5), E(6)); break;            \
        }                                                                  \
    } while (0)

__global__ __launch_bounds__(256, 6) void quanv_main_kernel(
    const float* __restrict__ in,   // (64,1,224,224)
    const float* __restrict__ w,    // (1,4)
    float* __restrict__ out)        // (64,4,223,223)
{
    __shared__ __half2 T01[TIR * TPITCH];   // 8064 B
    __shared__ __half2 T23[TIR * TPITCH];   // 8064 B
    __shared__ float wtr[8];

    const int tid = threadIdx.x;
    const int ib  = blockIdx.x;      // 0..27
    const int b   = blockIdx.y;
    const int X   = ib * RPB;

    const float* inb = in + (size_t)b * (H_IN * W_IN);

    if (tid < 4) {
        float s, c;
        __sincosf(__ldg(&w[tid]), &s, &c);
        wtr[tid] = c; wtr[4 + tid] = s;
    }

    // ---- Batched input loads: 504 slots (r = idx/56 in [0,9), g = idx%56),
    //      2 passes; float4 at (row X+r, col 4g) + scalar at col 4g+4.
    float4 vv[2]; float vx[2]; int rr_[2], gg[2]; bool act[2];
    #pragma unroll
    for (int p = 0; p < 2; p++) {
        const int idx = tid + 256 * p;
        act[p] = (idx < 504);
        const int r = idx / 56;
        const int g = idx - 56 * r;
        rr_[p] = r; gg[p] = g;
        if (act[p]) {
            int gr = X + r; if (gr > 223) gr = 223;
            const float* rp = inb + gr * W_IN + 4 * g;
            vv[p] = *reinterpret_cast<const float4*>(rp);
            int c4 = 4 * g + 4; if (c4 > 223) c4 = 223;
            vx[p] = __ldg(&inb[gr * W_IN + c4]);
        }
    }
    __syncthreads();   // weights ready

    const float cw0 = wtr[0], cw1 = wtr[1], cw2 = wtr[2], cw3 = wtr[3];
    const float sw0 = wtr[4], sw1 = wtr[5], sw2 = wtr[6], sw3 = wtr[7];

    // ---- Fold + pack + STS.128.
    #pragma unroll
    for (int p = 0; p < 2; p++) {
        if (!act[p]) continue;
        float vs[5] = {vv[p].x, vv[p].y, vv[p].z, vv[p].w, vx[p]};
        float sn[5], cs[5];
        #pragma unroll
        for (int j = 0; j < 5; j++) __sincosf(vs[j] * PI_F, &sn[j], &cs[j]);
        __half2 w01[4], w23[4];
        #pragma unroll
        for (int j = 0; j < 4; j++) {
            const float z0 = fmaf(-sn[j],     sw0, cs[j]     * cw0);
            const float z1 = fmaf(-sn[j + 1], sw1, cs[j + 1] * cw1);
            const float z2 = fmaf(-sn[j],     sw2, cs[j]     * cw2);
            const float z3 = fmaf(-sn[j + 1], sw3, cs[j + 1] * cw3);
            w01[j] = __floats2half2_rn(z0, z1);
            w23[j] = __floats2half2_rn(z2, z3);
        }
        const int base = rr_[p] * TPITCH + 4 * gg[p];
        *reinterpret_cast<uint4*>(&T01[base]) = *reinterpret_cast<uint4*>(w01);
        *reinterpret_cast<uint4*>(&T23[base]) = *reinterpret_cast<uint4*>(w23);
    }
    __syncthreads();   // tables ready

    const size_t obase = (size_t)b * 4 * PLANE;

    // ---- Quad consumer: (rx = tid>>6 + 4p in [0,8), q = tid&63 < 55).
    #pragma unroll
    for (int p = 0; p < 2; p++) {
        const int rx = (tid >> 6) + 4 * p;
        const int q  = tid & 63;
        const int x  = X + rx;
        if (q < 55 && x < L_OUT) {
            const int tb = rx * TPITCH + 4 * q;
            const uint4 a0 = *reinterpret_cast<const uint4*>(&T01[tb]);
            const uint4 a1 = *reinterpret_cast<const uint4*>(&T01[tb + 4]);
            const uint4 b0 = *reinterpret_cast<const uint4*>(&T23[tb + TPITCH]);
            const uint4 b1 = *reinterpret_cast<const uint4*>(&T23[tb + TPITCH + 4]);
            const uint32_t aw[8] = {a0.x, a0.y, a0.z, a0.w, a1.x, a1.y, a1.z, a1.w};
            const uint32_t bw[8] = {b0.x, b0.y, b0.z, b0.w, b1.x, b1.y, b1.z, b1.w};

            float p01[7], p23[7], z1v[7], z2v[7];
            #pragma unroll
            for (int i = 0; i < 7; i++) {
                const float2 z01 = __half22float2(*reinterpret_cast<const __half2*>(&aw[i]));
                const float2 z23 = __half22float2(*reinterpret_cast<const __half2*>(&bw[i]));
                p01[i] = z01.x * z01.y;
                p23[i] = z23.x * z23.y;
                z1v[i] = z01.y;
                z2v[i] = z23.x;
            }

            float* ob = out + obase + (size_t)x * L_OUT + 4 * q;
            int s;
            #define E0(i) (z1v[i] * p23[i])
            #define E1(i) (p01[i])
            #define E2(i) (p01[i] * z2v[i])
            #define E3(i) (p01[i] * p23[i])
            s = x & 3;        CASE_STORE(ob,             s, E0);   // ch0
            s = (x - 1) & 3;  CASE_STORE(ob + PLANE,     s, E1);   // ch1
            s = (x - 2) & 3;  CASE_STORE(ob + 2 * PLANE, s, E2);   // ch2
            s = (x - 3) & 3;  CASE_STORE(ob + 3 * PLANE, s, E3);   // ch3
            #undef E0
            #undef E1
            #undef E2
            #undef E3
        }
    }

    // ---- Edge scalars: per (row, ch) head y in [0,s) and tail [220+s, 223).
    if (tid < 128) {
        const int r = tid >> 4;          // 0..7
        const int e = tid & 15;
        if (e < 12) {
            const int ch = e & 3;
            const int k  = e >> 2;       // 0..2
            const int x  = X + r;
            if (x < L_OUT) {
                const int s = (x - ch) & 3;
                const int y = (k < s) ? k : (220 + k);
                const float2 z01 = __half22float2(T01[r * TPITCH + y]);
                const float2 z23 = __half22float2(T23[(r + 1) * TPITCH + y]);
                const float p01 = z01.x * z01.y;
                const float p23 = z23.x * z23.y;
                float val;
                if (ch == 0)      val = z01.y * p23;
                else if (ch == 1) val = p01;
                else if (ch == 2) val = p01 * z23.x;
                else              val = p01 * p23;
                out[obase + (size_t)ch * PLANE + (size_t)x * L_OUT + y] = val;
            }
        }
    }
}

extern "C" void kernel_launch(void* const* d_in, const int* in_sizes, int n_in,
                              void* d_out, int out_size) {
    const float* inputs = (const float*)d_in[0];   // (64,1,224,224) float32
    const float* weight = (const float*)d_in[1];   // (1,4) float32
    float* out = (float*)d_out;                    // (64,4,223,223) float32

    dim3 grid(28, 64);    // 28 row-groups x 64 batch
    quanv_main_kernel<<<grid, 256>>>(inputs, weight, out);
}